// round 2
// baseline (speedup 1.0000x reference)
#include <cuda_runtime.h>

#define Bsz 4096
#define D1  1024   // layer-1 K
#define H1  2048
#define H2  1024
#define NSTEPS 20
#define THRV 1.0f
#define BETAV 0.9f

// ---- persistent scratch (no allocs allowed) ----
__device__ float g_m1[Bsz * H1];
__device__ float g_m2[Bsz * H2];
__device__ float g_spk[Bsz * H2];
__device__ float g_s1[Bsz * H1];
__device__ float g_s2[Bsz * H2];
__device__ int   g_c1[NSTEPS];
__device__ int   g_c2[NSTEPS];
__device__ int   g_dead;

__global__ void init_kernel() {
    int idx = blockIdx.x * blockDim.x + threadIdx.x;
    int stride = gridDim.x * blockDim.x;
    for (int i = idx; i < Bsz * H1; i += stride) g_m1[i] = 0.f;
    for (int i = idx; i < Bsz * H2; i += stride) { g_m2[i] = 0.f; g_spk[i] = 0.f; }
    if (idx < NSTEPS) { g_c1[idx] = 0; g_c2[idx] = 0; }
    if (idx == 0) g_dead = 0;
}

// Fused GEMM (h = A @ W^T + bias) + Leaky membrane update + spike write + count.
// LAYER==1: A = (t==0 ? x : g_s2) [B x 1024], W=W1 [2048x1024], updates m1/s1
// LAYER==2: A = g_s1 [B x 2048],  W=W2 [1024x2048], updates m2/s2, spk_sum += s2
template <int LAYER>
__global__ void __launch_bounds__(256) step_kernel(
    const float* __restrict__ xext,
    const float* __restrict__ W,
    const float* __restrict__ bias,
    int t)
{
    if (*(volatile int*)&g_dead) return;   // network provably dead: no-op

    constexpr int N = (LAYER == 1) ? H1 : H2;
    constexpr int K = (LAYER == 1) ? D1 : H1;

    const float* A;
    bool dense;
    if (LAYER == 1) {
        if (t == 0) { A = xext; dense = true; }
        else        { A = g_s2; dense = (*(volatile int*)&g_c2[t - 1]) != 0; }
    } else {
        A = g_s1;  dense = (*(volatile int*)&g_c1[t]) != 0;
    }
    float* m    = (LAYER == 1) ? g_m1 : g_m2;
    float* sout = (LAYER == 1) ? g_s1 : g_s2;
    int*   ocnt = (LAYER == 1) ? &g_c1[t] : &g_c2[t];

    __shared__ float As[16][128];
    __shared__ float Ws[16][128];
    __shared__ int   wsum[8];

    const int tid = threadIdx.x;
    const int tx  = tid & 15;
    const int ty  = tid >> 4;
    const int bm  = blockIdx.y * 128;
    const int bn  = blockIdx.x * 128;

    float acc[8][8];
#pragma unroll
    for (int i = 0; i < 8; i++)
#pragma unroll
        for (int j = 0; j < 8; j++) acc[i][j] = 0.f;

    if (dense) {
        for (int k0 = 0; k0 < K; k0 += 16) {
#pragma unroll
            for (int l = 0; l < 2; l++) {
                int f   = tid + l * 256;           // 512 float4 per tile
                int row = f >> 2;
                int kq  = (f & 3) * 4;
                float4 av = *(const float4*)&A[(bm + row) * K + k0 + kq];
                As[kq + 0][row] = av.x; As[kq + 1][row] = av.y;
                As[kq + 2][row] = av.z; As[kq + 3][row] = av.w;
                float4 wv = *(const float4*)&W[(bn + row) * K + k0 + kq];
                Ws[kq + 0][row] = wv.x; Ws[kq + 1][row] = wv.y;
                Ws[kq + 2][row] = wv.z; Ws[kq + 3][row] = wv.w;
            }
            __syncthreads();
#pragma unroll
            for (int kk = 0; kk < 16; kk++) {
                float4 a0 = *(const float4*)&As[kk][ty * 8];
                float4 a1 = *(const float4*)&As[kk][ty * 8 + 4];
                float4 b0 = *(const float4*)&Ws[kk][tx * 8];
                float4 b1 = *(const float4*)&Ws[kk][tx * 8 + 4];
                float a[8] = {a0.x, a0.y, a0.z, a0.w, a1.x, a1.y, a1.z, a1.w};
                float b[8] = {b0.x, b0.y, b0.z, b0.w, b1.x, b1.y, b1.z, b1.w};
#pragma unroll
                for (int i = 0; i < 8; i++)
#pragma unroll
                    for (int j = 0; j < 8; j++) acc[i][j] += a[i] * b[j];
            }
            __syncthreads();
        }
    }

    // ---- epilogue: Leaky update (reset-by-subtraction) + spike ----
    int cnt = 0;
#pragma unroll
    for (int i = 0; i < 8; i++) {
        int row = bm + ty * 8 + i;
#pragma unroll
        for (int j = 0; j < 8; j++) {
            int col = bn + tx * 8 + j;
            int idx = row * N + col;
            float h  = acc[i][j] + bias[col];
            float mp = m[idx];
            float r  = (mp > THRV) ? 1.f : 0.f;
            float mn = BETAV * mp + h - r * THRV;
            float s  = (mn > THRV) ? 1.f : 0.f;
            m[idx]    = mn;
            sout[idx] = s;
            if (LAYER == 2) g_spk[idx] += s;
            cnt += (int)s;
        }
    }
#pragma unroll
    for (int o = 16; o > 0; o >>= 1) cnt += __shfl_down_sync(0xffffffff, cnt, o);
    if ((tid & 31) == 0) wsum[tid >> 5] = cnt;
    __syncthreads();
    if (tid == 0) {
        int tot = 0;
        for (int w = 0; w < 8; w++) tot += wsum[w];
        if (tot) atomicAdd(ocnt, tot);
    }
}

__global__ void check_dead_kernel(int t) {
    // no spikes this step anywhere => no membrane > THR => pure decay forever
    if (g_c1[t] == 0 && g_c2[t] == 0) g_dead = 1;
}

// out[B x 64] = (g_spk / NSTEPS) @ Wo^T + bo
__global__ void __launch_bounds__(256) final_kernel(
    const float* __restrict__ Wo, const float* __restrict__ bo,
    float* __restrict__ out)
{
    __shared__ float ssp[32][33];
    __shared__ float swo[64][33];
    const int tid  = threadIdx.x;
    const int row0 = blockIdx.x * 32;
    const int col  = tid & 63;
    const int rg   = tid >> 6;   // 0..3

    float acc[8];
#pragma unroll
    for (int r = 0; r < 8; r++) acc[r] = 0.f;

    for (int k0 = 0; k0 < H2; k0 += 32) {
        {
            int f = tid;                 // 256 float4 = 32x32 tile
            int row = f >> 3;
            int kq  = (f & 7) * 4;
            float4 v = *(const float4*)&g_spk[(row0 + row) * H2 + k0 + kq];
            ssp[row][kq + 0] = v.x; ssp[row][kq + 1] = v.y;
            ssp[row][kq + 2] = v.z; ssp[row][kq + 3] = v.w;
        }
#pragma unroll
        for (int l = 0; l < 2; l++) {
            int f = tid + l * 256;       // 512 float4 = 64x32 tile
            int row = f >> 3;
            int kq  = (f & 7) * 4;
            float4 v = *(const float4*)&Wo[row * H2 + k0 + kq];
            swo[row][kq + 0] = v.x; swo[row][kq + 1] = v.y;
            swo[row][kq + 2] = v.z; swo[row][kq + 3] = v.w;
        }
        __syncthreads();
#pragma unroll 8
        for (int kk = 0; kk < 32; kk++) {
            float w = swo[col][kk];
#pragma unroll
            for (int r = 0; r < 8; r++) acc[r] += ssp[rg + r * 4][kk] * w;
        }
        __syncthreads();
    }
#pragma unroll
    for (int r = 0; r < 8; r++)
        out[(row0 + rg + r * 4) * 64 + col] = acc[r] * (1.0f / NSTEPS) + bo[col];
}

extern "C" void kernel_launch(void* const* d_in, const int* in_sizes, int n_in,
                              void* d_out, int out_size)
{
    const float* x  = (const float*)d_in[0];
    const float* W1 = (const float*)d_in[1];
    const float* b1 = (const float*)d_in[2];
    const float* W2 = (const float*)d_in[3];
    const float* b2 = (const float*)d_in[4];
    const float* Wo = (const float*)d_in[5];
    const float* bo = (const float*)d_in[6];
    float* out = (float*)d_out;

    init_kernel<<<2048, 256>>>();
    for (int t = 0; t < NSTEPS; t++) {
        step_kernel<1><<<dim3(H1 / 128, Bsz / 128), 256>>>(x, W1, b1, t);
        step_kernel<2><<<dim3(H2 / 128, Bsz / 128), 256>>>(x, W2, b2, t);
        check_dead_kernel<<<1, 1>>>(t);
    }
    final_kernel<<<Bsz / 32, 256>>>(Wo, bo, out);
}

// round 5
// speedup vs baseline: 1.2518x; 1.2518x over previous
#include <cuda_runtime.h>

#define Bsz 4096
#define D1  1024   // layer-1 K
#define H1  2048
#define H2  1024
#define NSTEPS 20
#define THRV 1.0f
#define BETAV 0.9f

// ---- persistent scratch (identical layout to the R2 kernel that passed) ----
__device__ float g_m1[Bsz * H1];
__device__ float g_m2[Bsz * H2];
__device__ float g_spk[Bsz * H2];
__device__ float g_s1[Bsz * H1];
__device__ float g_s2[Bsz * H2];
__device__ int   g_c1[NSTEPS];
__device__ int   g_c2[NSTEPS];
__device__ int   g_dead;

__global__ void init_kernel() {
    int idx = blockIdx.x * blockDim.x + threadIdx.x;
    int stride = gridDim.x * blockDim.x;
    for (int i = idx; i < Bsz * H1; i += stride) g_m1[i] = 0.f;
    for (int i = idx; i < Bsz * H2; i += stride) { g_m2[i] = 0.f; g_spk[i] = 0.f; }
    if (idx < NSTEPS) { g_c1[idx] = 0; g_c2[idx] = 0; }
    if (idx == 0) g_dead = 0;
}

// Fused GEMM (h = A @ W^T + bias) + Leaky update + spike write + count.
// Identical to the passing R2 kernel except: per-k-column zero flags (nzk)
// let the FMA loop skip kk-columns whose entire 128-row A slice is zero.
// Skipping only drops exact +0.0 contributions -> bitwise-identical results.
template <int LAYER>
__global__ void __launch_bounds__(256) step_kernel(
    const float* __restrict__ xext,
    const float* __restrict__ W,
    const float* __restrict__ bias,
    int t)
{
    if (*(volatile int*)&g_dead) return;   // network provably dead: no-op

    constexpr int N = (LAYER == 1) ? H1 : H2;
    constexpr int K = (LAYER == 1) ? D1 : H1;

    const float* A;
    bool dense;
    if (LAYER == 1) {
        if (t == 0) { A = xext; dense = true; }
        else        { A = g_s2; dense = (*(volatile int*)&g_c2[t - 1]) != 0; }
    } else {
        A = g_s1;  dense = (*(volatile int*)&g_c1[t]) != 0;
    }
    float* m    = (LAYER == 1) ? g_m1 : g_m2;
    float* sout = (LAYER == 1) ? g_s1 : g_s2;
    int*   ocnt = (LAYER == 1) ? &g_c1[t] : &g_c2[t];

    __shared__ float As[16][128];
    __shared__ float Ws[16][128];
    __shared__ int   wsum[8];
    __shared__ int   nzk[2][16];   // per-k-column nonzero flags, parity buffered

    const int tid = threadIdx.x;
    const int tx  = tid & 15;
    const int ty  = tid >> 4;
    const int bm  = blockIdx.y * 128;
    const int bn  = blockIdx.x * 128;

    float acc[8][8];
#pragma unroll
    for (int i = 0; i < 8; i++)
#pragma unroll
        for (int j = 0; j < 8; j++) acc[i][j] = 0.f;

    if (dense) {
        if (tid < 32) nzk[tid >> 4][tid & 15] = 0;
        __syncthreads();

        for (int k0 = 0; k0 < K; k0 += 16) {
            const int p = (k0 >> 4) & 1;
#pragma unroll
            for (int l = 0; l < 2; l++) {
                int f   = tid + l * 256;           // 512 float4 per tile
                int row = f >> 2;
                int kq  = (f & 3) * 4;
                float4 av = *(const float4*)&A[(bm + row) * K + k0 + kq];
                As[kq + 0][row] = av.x; As[kq + 1][row] = av.y;
                As[kq + 2][row] = av.z; As[kq + 3][row] = av.w;
                // benign-race flag sets (all writers store 1)
                if (av.x != 0.f) nzk[p][kq + 0] = 1;
                if (av.y != 0.f) nzk[p][kq + 1] = 1;
                if (av.z != 0.f) nzk[p][kq + 2] = 1;
                if (av.w != 0.f) nzk[p][kq + 3] = 1;
                float4 wv = *(const float4*)&W[(bn + row) * K + k0 + kq];
                Ws[kq + 0][row] = wv.x; Ws[kq + 1][row] = wv.y;
                Ws[kq + 2][row] = wv.z; Ws[kq + 3][row] = wv.w;
            }
            __syncthreads();
#pragma unroll
            for (int kk = 0; kk < 16; kk++) {
                if (nzk[p][kk]) {
                    float4 a0 = *(const float4*)&As[kk][ty * 8];
                    float4 a1 = *(const float4*)&As[kk][ty * 8 + 4];
                    float4 b0 = *(const float4*)&Ws[kk][tx * 8];
                    float4 b1 = *(const float4*)&Ws[kk][tx * 8 + 4];
                    float a[8] = {a0.x, a0.y, a0.z, a0.w, a1.x, a1.y, a1.z, a1.w};
                    float b[8] = {b0.x, b0.y, b0.z, b0.w, b1.x, b1.y, b1.z, b1.w};
#pragma unroll
                    for (int i = 0; i < 8; i++)
#pragma unroll
                        for (int j = 0; j < 8; j++) acc[i][j] += a[i] * b[j];
                }
            }
            // reset the OTHER parity's flags for the next iteration; separated
            // from that iteration's setters by the loop-ending __syncthreads
            if (tid < 16) nzk[p ^ 1][tid] = 0;
            __syncthreads();
        }
    }

    // ---- epilogue: Leaky update (reset-by-subtraction) + spike ----
    int cnt = 0;
#pragma unroll
    for (int i = 0; i < 8; i++) {
        int row = bm + ty * 8 + i;
#pragma unroll
        for (int j = 0; j < 8; j++) {
            int col = bn + tx * 8 + j;
            int idx = row * N + col;
            float h  = acc[i][j] + bias[col];
            float mp = m[idx];
            float r  = (mp > THRV) ? 1.f : 0.f;
            float mn = BETAV * mp + h - r * THRV;
            float s  = (mn > THRV) ? 1.f : 0.f;
            m[idx]    = mn;
            sout[idx] = s;
            if (LAYER == 2) g_spk[idx] += s;
            cnt += (int)s;
        }
    }
#pragma unroll
    for (int o = 16; o > 0; o >>= 1) cnt += __shfl_down_sync(0xffffffff, cnt, o);
    if ((tid & 31) == 0) wsum[tid >> 5] = cnt;
    __syncthreads();
    if (tid == 0) {
        int tot = 0;
        for (int w = 0; w < 8; w++) tot += wsum[w];
        if (tot) atomicAdd(ocnt, tot);
    }
}

__global__ void check_dead_kernel(int t) {
    // no spikes this step anywhere => no membrane > THR => pure decay forever
    if (g_c1[t] == 0 && g_c2[t] == 0) g_dead = 1;
}

// out[B x 64] = (g_spk / NSTEPS) @ Wo^T + bo
__global__ void __launch_bounds__(256) final_kernel(
    const float* __restrict__ Wo, const float* __restrict__ bo,
    float* __restrict__ out)
{
    __shared__ float ssp[32][33];
    __shared__ float swo[64][33];
    const int tid  = threadIdx.x;
    const int row0 = blockIdx.x * 32;
    const int col  = tid & 63;
    const int rg   = tid >> 6;   // 0..3

    float acc[8];
#pragma unroll
    for (int r = 0; r < 8; r++) acc[r] = 0.f;

    for (int k0 = 0; k0 < H2; k0 += 32) {
        {
            int f = tid;                 // 256 float4 = 32x32 tile
            int row = f >> 3;
            int kq  = (f & 7) * 4;
            float4 v = *(const float4*)&g_spk[(row0 + row) * H2 + k0 + kq];
            ssp[row][kq + 0] = v.x; ssp[row][kq + 1] = v.y;
            ssp[row][kq + 2] = v.z; ssp[row][kq + 3] = v.w;
        }
#pragma unroll
        for (int l = 0; l < 2; l++) {
            int f = tid + l * 256;       // 512 float4 = 64x32 tile
            int row = f >> 3;
            int kq  = (f & 7) * 4;
            float4 v = *(const float4*)&Wo[row * H2 + k0 + kq];
            swo[row][kq + 0] = v.x; swo[row][kq + 1] = v.y;
            swo[row][kq + 2] = v.z; swo[row][kq + 3] = v.w;
        }
        __syncthreads();
#pragma unroll 8
        for (int kk = 0; kk < 32; kk++) {
            float w = swo[col][kk];
#pragma unroll
            for (int r = 0; r < 8; r++) acc[r] += ssp[rg + r * 4][kk] * w;
        }
        __syncthreads();
    }
#pragma unroll
    for (int r = 0; r < 8; r++)
        out[(row0 + rg + r * 4) * 64 + col] = acc[r] * (1.0f / NSTEPS) + bo[col];
}

extern "C" void kernel_launch(void* const* d_in, const int* in_sizes, int n_in,
                              void* d_out, int out_size)
{
    const float* x  = (const float*)d_in[0];
    const float* W1 = (const float*)d_in[1];
    const float* b1 = (const float*)d_in[2];
    const float* W2 = (const float*)d_in[3];
    const float* b2 = (const float*)d_in[4];
    const float* Wo = (const float*)d_in[5];
    const float* bo = (const float*)d_in[6];
    float* out = (float*)d_out;

    init_kernel<<<2048, 256>>>();
    for (int t = 0; t < NSTEPS; t++) {
        step_kernel<1><<<dim3(H1 / 128, Bsz / 128), 256>>>(x, W1, b1, t);
        step_kernel<2><<<dim3(H2 / 128, Bsz / 128), 256>>>(x, W2, b2, t);
        check_dead_kernel<<<1, 1>>>(t);
    }
    final_kernel<<<Bsz / 32, 256>>>(Wo, bo, out);
}

// round 6
// speedup vs baseline: 1.5805x; 1.2625x over previous
#include <cuda_runtime.h>

#define Bsz 4096
#define D1  1024   // layer-1 K
#define H1  2048
#define H2  1024
#define NSTEPS 20
#define THRV 1.0f
#define BETAV 0.9f
#define SPARSE_THRESH 8192

#define MW1 (H1/32)   // 64 mask words per s1 row
#define MW2 (H2/32)   // 32 mask words per s2 row

// ---- persistent scratch (no allocs allowed) ----
__device__ float g_m1[Bsz * H1];
__device__ float g_m2[Bsz * H2];
__device__ float g_spk[Bsz * H2];
__device__ float g_s1[Bsz * H1];
__device__ float g_s2[Bsz * H2];
__device__ unsigned g_mk1[Bsz * MW1];   // s1 spike bitmasks (rewritten each step)
__device__ unsigned g_mk2[Bsz * MW2];   // s2 spike bitmasks
__device__ int   g_c1[NSTEPS];
__device__ int   g_c2[NSTEPS];

__global__ void init_kernel() {
    int idx = blockIdx.x * blockDim.x + threadIdx.x;
    int stride = gridDim.x * blockDim.x;
    for (int i = idx; i < Bsz * H1; i += stride) g_m1[i] = 0.f;
    for (int i = idx; i < Bsz * H2; i += stride) { g_m2[i] = 0.f; g_spk[i] = 0.f; }
    if (idx < NSTEPS) { g_c1[idx] = 0; g_c2[idx] = 0; }
}

// Fused linear (h = A @ W^T + bias) + Leaky update + spike/mask write + count.
// Dense path: R5's proven tiled GEMM with per-k-column zero skip.
// Sparse path (input spikes < SPARSE_THRESH): mask-driven gather of W rows.
// Both accumulate in ascending k with only exact +0.0 terms differing ->
// bitwise-identical results.
template <int LAYER>
__global__ void __launch_bounds__(256) step_kernel(
    const float* __restrict__ xext,
    const float* __restrict__ W,
    const float* __restrict__ bias,
    int t)
{
    // liveness: zero spikes in both layers at the previous boundary =>
    // all membranes <= THR and zero input forever => provably inert.
    if (LAYER == 1) {
        if (t > 0 && g_c1[t - 1] == 0 && g_c2[t - 1] == 0) return;
    } else {
        if (g_c1[t] == 0 && (t == 0 || g_c2[t - 1] == 0)) return;
    }

    constexpr int N  = (LAYER == 1) ? H1 : H2;
    constexpr int K  = (LAYER == 1) ? D1 : H1;
    constexpr int KW = K / 32;
    constexpr int MW = (LAYER == 1) ? MW1 : MW2;

    const float* A;
    int incnt;
    if (LAYER == 1) {
        if (t == 0) { A = xext; incnt = 0x40000000; }          // force dense
        else        { A = g_s2; incnt = g_c2[t - 1]; }
    } else {
        A = g_s1; incnt = g_c1[t];
    }
    float* m    = (LAYER == 1) ? g_m1 : g_m2;
    float* sout = (LAYER == 1) ? g_s1 : g_s2;
    const unsigned* gmin = (LAYER == 1) ? g_mk2 : g_mk1;       // input masks
    unsigned* gmout      = (LAYER == 1) ? g_mk1 : g_mk2;       // output masks
    int* ocnt            = (LAYER == 1) ? &g_c1[t] : &g_c2[t];

    // shared: dense path uses As/Ws (16KB); sparse path uses smask (<=32KB);
    // stg (2KB at +32KB) is disjoint from both.
    __shared__ __align__(16) unsigned char sraw[34 * 1024];
    float (*As)[128] = (float (*)[128])sraw;
    float (*Ws)[128] = (float (*)[128])(sraw + 8192);
    unsigned* smask  = (unsigned*)sraw;
    unsigned* stg    = (unsigned*)(sraw + 32768);
    __shared__ int wsum[8];
    __shared__ int nzk[2][16];

    const int tid = threadIdx.x;
    const int tx  = tid & 15;
    const int ty  = tid >> 4;
    const int bm  = blockIdx.y * 128;
    const int bn  = blockIdx.x * 128;

    float acc[8][8];
#pragma unroll
    for (int i = 0; i < 8; i++)
#pragma unroll
        for (int j = 0; j < 8; j++) acc[i][j] = 0.f;

    if (incnt > SPARSE_THRESH) {
        // ---------- dense tiled GEMM (proven R5 path) ----------
        if (tid < 32) nzk[tid >> 4][tid & 15] = 0;
        __syncthreads();

        for (int k0 = 0; k0 < K; k0 += 16) {
            const int p = (k0 >> 4) & 1;
#pragma unroll
            for (int l = 0; l < 2; l++) {
                int f   = tid + l * 256;
                int row = f >> 2;
                int kq  = (f & 3) * 4;
                float4 av = *(const float4*)&A[(bm + row) * K + k0 + kq];
                As[kq + 0][row] = av.x; As[kq + 1][row] = av.y;
                As[kq + 2][row] = av.z; As[kq + 3][row] = av.w;
                if (av.x != 0.f) nzk[p][kq + 0] = 1;
                if (av.y != 0.f) nzk[p][kq + 1] = 1;
                if (av.z != 0.f) nzk[p][kq + 2] = 1;
                if (av.w != 0.f) nzk[p][kq + 3] = 1;
                float4 wv = *(const float4*)&W[(bn + row) * K + k0 + kq];
                Ws[kq + 0][row] = wv.x; Ws[kq + 1][row] = wv.y;
                Ws[kq + 2][row] = wv.z; Ws[kq + 3][row] = wv.w;
            }
            __syncthreads();
#pragma unroll
            for (int kk = 0; kk < 16; kk++) {
                if (nzk[p][kk]) {
                    float4 a0 = *(const float4*)&As[kk][ty * 8];
                    float4 a1 = *(const float4*)&As[kk][ty * 8 + 4];
                    float4 b0 = *(const float4*)&Ws[kk][tx * 8];
                    float4 b1 = *(const float4*)&Ws[kk][tx * 8 + 4];
                    float a[8] = {a0.x, a0.y, a0.z, a0.w, a1.x, a1.y, a1.z, a1.w};
                    float b[8] = {b0.x, b0.y, b0.z, b0.w, b1.x, b1.y, b1.z, b1.w};
#pragma unroll
                    for (int i = 0; i < 8; i++)
#pragma unroll
                        for (int j = 0; j < 8; j++) acc[i][j] += a[i] * b[j];
                }
            }
            if (tid < 16) nzk[p ^ 1][tid] = 0;
            __syncthreads();
        }
    } else if (incnt > 0) {
        // ---------- sparse mask-driven gather ----------
        for (int idx = tid; idx < 128 * KW; idx += 256)
            smask[idx] = gmin[(bm + idx / KW) * KW + (idx % KW)];
        __syncthreads();
#pragma unroll
        for (int i = 0; i < 8; i++) {
            const unsigned* mrow = &smask[(ty * 8 + i) * KW];
            for (int w = 0; w < KW; w++) {
                unsigned word = mrow[w];
                while (word) {
                    int bit = __ffs(word) - 1;
                    word &= word - 1;
                    const float* wp = &W[(size_t)(bn + tx * 8) * K + w * 32 + bit];
#pragma unroll
                    for (int j = 0; j < 8; j++)
                        acc[i][j] += wp[(size_t)j * K];
                }
            }
        }
        __syncthreads();
    }
    // incnt == 0: acc stays 0 -> pure decay/reset epilogue

    // ---- epilogue: Leaky update + spike + mask staging ----
    if (tid < 256) { stg[tid] = 0u; stg[tid + 256] = 0u; }
    __syncthreads();

    int cnt = 0;
#pragma unroll
    for (int i = 0; i < 8; i++) {
        int row = bm + ty * 8 + i;
#pragma unroll
        for (int j = 0; j < 8; j++) {
            int col = bn + tx * 8 + j;
            int idx = row * N + col;
            float h  = acc[i][j] + bias[col];
            float mp = m[idx];
            float r  = (mp > THRV) ? 1.f : 0.f;
            float mn = BETAV * mp + h - r * THRV;
            float s  = (mn > THRV) ? 1.f : 0.f;
            m[idx]    = mn;
            sout[idx] = s;
            if (s != 0.f) {
                if (LAYER == 2) g_spk[idx] += 1.f;
                int cb = tx * 8 + j;
                atomicOr(&stg[(ty * 8 + i) * 4 + (cb >> 5)], 1u << (cb & 31));
                cnt++;
            }
        }
    }
    __syncthreads();

    // write output masks (block owns rows [bm,bm+128), words [bn/32, bn/32+4))
    for (int q = tid; q < 512; q += 256) {
        int r = q >> 2, w = q & 3;
        gmout[(bm + r) * MW + (bn >> 5) + w] = stg[q];
    }

#pragma unroll
    for (int o = 16; o > 0; o >>= 1) cnt += __shfl_down_sync(0xffffffff, cnt, o);
    if ((tid & 31) == 0) wsum[tid >> 5] = cnt;
    __syncthreads();
    if (tid == 0) {
        int tot = 0;
        for (int w = 0; w < 8; w++) tot += wsum[w];
        if (tot) atomicAdd(ocnt, tot);
    }
}

// out[B x 64] = (g_spk / NSTEPS) @ Wo^T + bo   (proven R2/R5 kernel)
__global__ void __launch_bounds__(256) final_kernel(
    const float* __restrict__ Wo, const float* __restrict__ bo,
    float* __restrict__ out)
{
    __shared__ float ssp[32][33];
    __shared__ float swo[64][33];
    const int tid  = threadIdx.x;
    const int row0 = blockIdx.x * 32;
    const int col  = tid & 63;
    const int rg   = tid >> 6;

    float acc[8];
#pragma unroll
    for (int r = 0; r < 8; r++) acc[r] = 0.f;

    for (int k0 = 0; k0 < H2; k0 += 32) {
        {
            int f = tid;
            int row = f >> 3;
            int kq  = (f & 7) * 4;
            float4 v = *(const float4*)&g_spk[(row0 + row) * H2 + k0 + kq];
            ssp[row][kq + 0] = v.x; ssp[row][kq + 1] = v.y;
            ssp[row][kq + 2] = v.z; ssp[row][kq + 3] = v.w;
        }
#pragma unroll
        for (int l = 0; l < 2; l++) {
            int f = tid + l * 256;
            int row = f >> 3;
            int kq  = (f & 7) * 4;
            float4 v = *(const float4*)&Wo[row * H2 + k0 + kq];
            swo[row][kq + 0] = v.x; swo[row][kq + 1] = v.y;
            swo[row][kq + 2] = v.z; swo[row][kq + 3] = v.w;
        }
        __syncthreads();
#pragma unroll 8
        for (int kk = 0; kk < 32; kk++) {
            float w = swo[col][kk];
#pragma unroll
            for (int r = 0; r < 8; r++) acc[r] += ssp[rg + r * 4][kk] * w;
        }
        __syncthreads();
    }
#pragma unroll
    for (int r = 0; r < 8; r++)
        out[(row0 + rg + r * 4) * 64 + col] = acc[r] * (1.0f / NSTEPS) + bo[col];
}

extern "C" void kernel_launch(void* const* d_in, const int* in_sizes, int n_in,
                              void* d_out, int out_size)
{
    const float* x  = (const float*)d_in[0];
    const float* W1 = (const float*)d_in[1];
    const float* b1 = (const float*)d_in[2];
    const float* W2 = (const float*)d_in[3];
    const float* b2 = (const float*)d_in[4];
    const float* Wo = (const float*)d_in[5];
    const float* bo = (const float*)d_in[6];
    float* out = (float*)d_out;

    init_kernel<<<2048, 256>>>();
    for (int t = 0; t < NSTEPS; t++) {
        step_kernel<1><<<dim3(H1 / 128, Bsz / 128), 256>>>(x, W1, b1, t);
        step_kernel<2><<<dim3(H2 / 128, Bsz / 128), 256>>>(x, W2, b2, t);
    }
    final_kernel<<<Bsz / 32, 256>>>(Wo, bo, out);
}

// round 7
// speedup vs baseline: 1.6600x; 1.0503x over previous
#include <cuda_runtime.h>

#define Bsz 4096
#define D1  1024   // layer-1 K
#define H1  2048
#define H2  1024
#define NSTEPS 20
#define THRV 1.0f
#define BETAV 0.9f
#define SPARSE_THRESH 8192

#define MW1 (H1/32)   // 64 mask words per s1 row
#define MW2 (H2/32)   // 32 mask words per s2 row

// ---- persistent scratch (no allocs allowed) ----
__device__ float g_m1[Bsz * H1];
__device__ float g_m2[Bsz * H2];
__device__ float g_spk[Bsz * H2];
__device__ float g_s1[Bsz * H1];
__device__ float g_s2[Bsz * H2];
__device__ float g_W1T[D1 * H1];        // W1T[c*H1+n] = W1[n*D1+c]
__device__ float g_W2T[H1 * H2];        // W2T[c*H2+n] = W2[n*H1+c]
__device__ unsigned g_mk1[Bsz * MW1];   // s1 spike bitmasks (rewritten each step)
__device__ unsigned g_mk2[Bsz * MW2];   // s2 spike bitmasks
__device__ int   g_c1[NSTEPS];
__device__ int   g_c2[NSTEPS];

__global__ void init_kernel(const float* __restrict__ W1,
                            const float* __restrict__ W2) {
    int idx = blockIdx.x * blockDim.x + threadIdx.x;
    int stride = gridDim.x * blockDim.x;
    for (int i = idx; i < Bsz * H1; i += stride) g_m1[i] = 0.f;
    for (int i = idx; i < Bsz * H2; i += stride) { g_m2[i] = 0.f; g_spk[i] = 0.f; }
    // transposes: write-coalesced (n fastest), reads strided (one-time cost)
    for (int i = idx; i < D1 * H1; i += stride) {
        int c = i / H1, n = i % H1;
        g_W1T[i] = W1[n * D1 + c];
    }
    for (int i = idx; i < H1 * H2; i += stride) {
        int c = i / H2, n = i % H2;
        g_W2T[i] = W2[n * H1 + c];
    }
    if (idx < NSTEPS) { g_c1[idx] = 0; g_c2[idx] = 0; }
}

// Fused linear (h = A @ W^T + bias) + Leaky update + spike/mask write + count.
// FORCE_DENSE (t==0): clean dense tiled GEMM (no nzk overhead).
// Otherwise: dense-with-nzk fallback (incnt large) or coalesced mask-driven
// gather from transposed weights. All variants accumulate in ascending k and
// differ only in exact +0.0 terms -> bitwise-identical results.
template <int LAYER, bool FORCE_DENSE>
__global__ void __launch_bounds__(256) step_kernel(
    const float* __restrict__ xext,
    const float* __restrict__ W,
    const float* __restrict__ bias,
    int t)
{
    // liveness: zero spikes in both layers at the previous boundary =>
    // all membranes <= THR and zero input forever => provably inert.
    if (LAYER == 1) {
        if (t > 0 && g_c1[t - 1] == 0 && g_c2[t - 1] == 0) return;
    } else {
        if (g_c1[t] == 0 && (t == 0 || g_c2[t - 1] == 0)) return;
    }

    constexpr int N  = (LAYER == 1) ? H1 : H2;
    constexpr int K  = (LAYER == 1) ? D1 : H1;
    constexpr int KW = K / 32;
    constexpr int MW = (LAYER == 1) ? MW1 : MW2;

    const float* A;
    int incnt;
    if (LAYER == 1) {
        if (t == 0) { A = xext; incnt = 0x40000000; }
        else        { A = g_s2; incnt = g_c2[t - 1]; }
    } else {
        A = g_s1; incnt = g_c1[t];
    }
    float* m    = (LAYER == 1) ? g_m1 : g_m2;
    float* sout = (LAYER == 1) ? g_s1 : g_s2;
    const unsigned* gmin = (LAYER == 1) ? g_mk2 : g_mk1;
    unsigned* gmout      = (LAYER == 1) ? g_mk1 : g_mk2;
    int* ocnt            = (LAYER == 1) ? &g_c1[t] : &g_c2[t];

    __shared__ __align__(16) unsigned char sraw[34 * 1024];
    float (*As)[128] = (float (*)[128])sraw;
    float (*Ws)[128] = (float (*)[128])(sraw + 8192);
    unsigned* smask  = (unsigned*)sraw;
    unsigned* stg    = (unsigned*)(sraw + 32768);
    __shared__ int wsum[8];
    __shared__ int nzk[2][16];

    const int tid = threadIdx.x;
    const int tx  = tid & 15;
    const int ty  = tid >> 4;
    const int bm  = blockIdx.y * 128;
    const int bn  = blockIdx.x * 128;

    float acc[8][8];
#pragma unroll
    for (int i = 0; i < 8; i++)
#pragma unroll
        for (int j = 0; j < 8; j++) acc[i][j] = 0.f;

    if (FORCE_DENSE) {
        // ---------- clean dense tiled GEMM ----------
        for (int k0 = 0; k0 < K; k0 += 16) {
#pragma unroll
            for (int l = 0; l < 2; l++) {
                int f   = tid + l * 256;
                int row = f >> 2;
                int kq  = (f & 3) * 4;
                float4 av = *(const float4*)&A[(bm + row) * K + k0 + kq];
                As[kq + 0][row] = av.x; As[kq + 1][row] = av.y;
                As[kq + 2][row] = av.z; As[kq + 3][row] = av.w;
                float4 wv = *(const float4*)&W[(bn + row) * K + k0 + kq];
                Ws[kq + 0][row] = wv.x; Ws[kq + 1][row] = wv.y;
                Ws[kq + 2][row] = wv.z; Ws[kq + 3][row] = wv.w;
            }
            __syncthreads();
#pragma unroll
            for (int kk = 0; kk < 16; kk++) {
                float4 a0 = *(const float4*)&As[kk][ty * 8];
                float4 a1 = *(const float4*)&As[kk][ty * 8 + 4];
                float4 b0 = *(const float4*)&Ws[kk][tx * 8];
                float4 b1 = *(const float4*)&Ws[kk][tx * 8 + 4];
                float a[8] = {a0.x, a0.y, a0.z, a0.w, a1.x, a1.y, a1.z, a1.w};
                float b[8] = {b0.x, b0.y, b0.z, b0.w, b1.x, b1.y, b1.z, b1.w};
#pragma unroll
                for (int i = 0; i < 8; i++)
#pragma unroll
                    for (int j = 0; j < 8; j++) acc[i][j] += a[i] * b[j];
            }
            __syncthreads();
        }
    } else if (incnt > SPARSE_THRESH) {
        // ---------- dense tiled GEMM with per-k-column zero skip ----------
        if (tid < 32) nzk[tid >> 4][tid & 15] = 0;
        __syncthreads();
        for (int k0 = 0; k0 < K; k0 += 16) {
            const int p = (k0 >> 4) & 1;
#pragma unroll
            for (int l = 0; l < 2; l++) {
                int f   = tid + l * 256;
                int row = f >> 2;
                int kq  = (f & 3) * 4;
                float4 av = *(const float4*)&A[(bm + row) * K + k0 + kq];
                As[kq + 0][row] = av.x; As[kq + 1][row] = av.y;
                As[kq + 2][row] = av.z; As[kq + 3][row] = av.w;
                if (av.x != 0.f) nzk[p][kq + 0] = 1;
                if (av.y != 0.f) nzk[p][kq + 1] = 1;
                if (av.z != 0.f) nzk[p][kq + 2] = 1;
                if (av.w != 0.f) nzk[p][kq + 3] = 1;
                float4 wv = *(const float4*)&W[(bn + row) * K + k0 + kq];
                Ws[kq + 0][row] = wv.x; Ws[kq + 1][row] = wv.y;
                Ws[kq + 2][row] = wv.z; Ws[kq + 3][row] = wv.w;
            }
            __syncthreads();
#pragma unroll
            for (int kk = 0; kk < 16; kk++) {
                if (nzk[p][kk]) {
                    float4 a0 = *(const float4*)&As[kk][ty * 8];
                    float4 a1 = *(const float4*)&As[kk][ty * 8 + 4];
                    float4 b0 = *(const float4*)&Ws[kk][tx * 8];
                    float4 b1 = *(const float4*)&Ws[kk][tx * 8 + 4];
                    float a[8] = {a0.x, a0.y, a0.z, a0.w, a1.x, a1.y, a1.z, a1.w};
                    float b[8] = {b0.x, b0.y, b0.z, b0.w, b1.x, b1.y, b1.z, b1.w};
#pragma unroll
                    for (int i = 0; i < 8; i++)
#pragma unroll
                        for (int j = 0; j < 8; j++) acc[i][j] += a[i] * b[j];
                }
            }
            if (tid < 16) nzk[p ^ 1][tid] = 0;
            __syncthreads();
        }
    } else if (incnt > 0) {
        // ---------- sparse gather from transposed weights (coalesced) ----------
        const float* WT = (LAYER == 1) ? g_W1T : g_W2T;   // [K][N]
        for (int idx = tid; idx < 128 * KW; idx += 256)
            smask[idx] = gmin[(bm + idx / KW) * KW + (idx % KW)];
        __syncthreads();
#pragma unroll
        for (int i = 0; i < 8; i++) {
            const unsigned* mrow = &smask[(ty * 8 + i) * KW];
            for (int w = 0; w < KW; w++) {
                unsigned word = mrow[w];
                while (word) {
                    int bit = __ffs(word) - 1;
                    word &= word - 1;
                    const float4* wp = (const float4*)&WT[(size_t)(w * 32 + bit) * N + bn + tx * 8];
                    float4 w0 = wp[0];
                    float4 w1 = wp[1];
                    acc[i][0] += w0.x; acc[i][1] += w0.y;
                    acc[i][2] += w0.z; acc[i][3] += w0.w;
                    acc[i][4] += w1.x; acc[i][5] += w1.y;
                    acc[i][6] += w1.z; acc[i][7] += w1.w;
                }
            }
        }
        __syncthreads();
    }
    // incnt == 0: acc stays 0 -> pure decay/reset epilogue

    // ---- epilogue: Leaky update + spike + mask staging ----
    if (tid < 256) { stg[tid] = 0u; stg[tid + 256] = 0u; }
    __syncthreads();

    int cnt = 0;
#pragma unroll
    for (int i = 0; i < 8; i++) {
        int row = bm + ty * 8 + i;
#pragma unroll
        for (int j = 0; j < 8; j++) {
            int col = bn + tx * 8 + j;
            int idx = row * N + col;
            float h  = acc[i][j] + bias[col];
            float mp = m[idx];
            float r  = (mp > THRV) ? 1.f : 0.f;
            float mn = BETAV * mp + h - r * THRV;
            float s  = (mn > THRV) ? 1.f : 0.f;
            m[idx]    = mn;
            sout[idx] = s;
            if (s != 0.f) {
                if (LAYER == 2) g_spk[idx] += 1.f;
                int cb = tx * 8 + j;
                atomicOr(&stg[(ty * 8 + i) * 4 + (cb >> 5)], 1u << (cb & 31));
                cnt++;
            }
        }
    }
    __syncthreads();

    for (int q = tid; q < 512; q += 256) {
        int r = q >> 2, w = q & 3;
        gmout[(bm + r) * MW + (bn >> 5) + w] = stg[q];
    }

#pragma unroll
    for (int o = 16; o > 0; o >>= 1) cnt += __shfl_down_sync(0xffffffff, cnt, o);
    if ((tid & 31) == 0) wsum[tid >> 5] = cnt;
    __syncthreads();
    if (tid == 0) {
        int tot = 0;
        for (int w = 0; w < 8; w++) tot += wsum[w];
        if (tot) atomicAdd(ocnt, tot);
    }
}

// out[B x 64] = (g_spk / NSTEPS) @ Wo^T + bo   (proven kernel)
__global__ void __launch_bounds__(256) final_kernel(
    const float* __restrict__ Wo, const float* __restrict__ bo,
    float* __restrict__ out)
{
    __shared__ float ssp[32][33];
    __shared__ float swo[64][33];
    const int tid  = threadIdx.x;
    const int row0 = blockIdx.x * 32;
    const int col  = tid & 63;
    const int rg   = tid >> 6;

    float acc[8];
#pragma unroll
    for (int r = 0; r < 8; r++) acc[r] = 0.f;

    for (int k0 = 0; k0 < H2; k0 += 32) {
        {
            int f = tid;
            int row = f >> 3;
            int kq  = (f & 7) * 4;
            float4 v = *(const float4*)&g_spk[(row0 + row) * H2 + k0 + kq];
            ssp[row][kq + 0] = v.x; ssp[row][kq + 1] = v.y;
            ssp[row][kq + 2] = v.z; ssp[row][kq + 3] = v.w;
        }
#pragma unroll
        for (int l = 0; l < 2; l++) {
            int f = tid + l * 256;
            int row = f >> 3;
            int kq  = (f & 7) * 4;
            float4 v = *(const float4*)&Wo[row * H2 + k0 + kq];
            swo[row][kq + 0] = v.x; swo[row][kq + 1] = v.y;
            swo[row][kq + 2] = v.z; swo[row][kq + 3] = v.w;
        }
        __syncthreads();
#pragma unroll 8
        for (int kk = 0; kk < 32; kk++) {
            float w = swo[col][kk];
#pragma unroll
            for (int r = 0; r < 8; r++) acc[r] += ssp[rg + r * 4][kk] * w;
        }
        __syncthreads();
    }
#pragma unroll
    for (int r = 0; r < 8; r++)
        out[(row0 + rg + r * 4) * 64 + col] = acc[r] * (1.0f / NSTEPS) + bo[col];
}

extern "C" void kernel_launch(void* const* d_in, const int* in_sizes, int n_in,
                              void* d_out, int out_size)
{
    const float* x  = (const float*)d_in[0];
    const float* W1 = (const float*)d_in[1];
    const float* b1 = (const float*)d_in[2];
    const float* W2 = (const float*)d_in[3];
    const float* b2 = (const float*)d_in[4];
    const float* Wo = (const float*)d_in[5];
    const float* bo = (const float*)d_in[6];
    float* out = (float*)d_out;

    init_kernel<<<2048, 256>>>(W1, W2);
    // t = 0: dense (x is dense; s1 at ~6% density never skips anyway)
    step_kernel<1, true><<<dim3(H1 / 128, Bsz / 128), 256>>>(x, W1, b1, 0);
    step_kernel<2, true><<<dim3(H2 / 128, Bsz / 128), 256>>>(x, W2, b2, 0);
    for (int t = 1; t < NSTEPS; t++) {
        step_kernel<1, false><<<dim3(H1 / 128, Bsz / 128), 256>>>(x, W1, b1, t);
        step_kernel<2, false><<<dim3(H2 / 128, Bsz / 128), 256>>>(x, W2, b2, t);
    }
    final_kernel<<<Bsz / 32, 256>>>(Wo, bo, out);
}

// round 8
// speedup vs baseline: 1.6616x; 1.0010x over previous
#include <cuda_runtime.h>

#define Bsz 4096
#define D1  1024   // layer-1 K
#define H1  2048
#define H2  1024
#define NSTEPS 20
#define THRV 1.0f
#define BETAV 0.9f
#define SPARSE_THRESH 8192

#define MW1 (H1/32)   // 64 mask words per s1 row
#define MW2 (H2/32)   // 32 mask words per s2 row

// ---- persistent scratch (no allocs allowed) ----
__device__ float g_m1[Bsz * H1];
__device__ float g_m2[Bsz * H2];
__device__ float g_spk[Bsz * H2];
__device__ float g_s1[Bsz * H1];
__device__ float g_s2[Bsz * H2];
__device__ float g_W1T[D1 * H1];        // W1T[c*H1+n] = W1[n*D1+c]
__device__ float g_W2T[H1 * H2];        // W2T[c*H2+n] = W2[n*H1+c]
__device__ unsigned g_mk1[Bsz * MW1];   // s1 spike bitmasks (rewritten each step)
__device__ unsigned g_mk2[Bsz * MW2];   // s2 spike bitmasks
__device__ int   g_c1[NSTEPS];
__device__ int   g_c2[NSTEPS];

__global__ void init_kernel(const float* __restrict__ W1,
                            const float* __restrict__ W2) {
    int idx = blockIdx.x * blockDim.x + threadIdx.x;
    int stride = gridDim.x * blockDim.x;
    for (int i = idx; i < Bsz * H1; i += stride) g_m1[i] = 0.f;
    for (int i = idx; i < Bsz * H2; i += stride) { g_m2[i] = 0.f; g_spk[i] = 0.f; }
    // transposes: write-coalesced (n fastest), reads strided (one-time cost)
    for (int i = idx; i < D1 * H1; i += stride) {
        int c = i / H1, n = i % H1;
        g_W1T[i] = W1[n * D1 + c];
    }
    for (int i = idx; i < H1 * H2; i += stride) {
        int c = i / H2, n = i % H2;
        g_W2T[i] = W2[n * H1 + c];
    }
    if (idx < NSTEPS) { g_c1[idx] = 0; g_c2[idx] = 0; }
}

// Fused linear (h = A @ W^T + bias) + Leaky update + spike/mask write + count.
// FORCE_DENSE (t==0): clean dense tiled GEMM (no nzk overhead).
// Otherwise: dense-with-nzk fallback (incnt large) or coalesced mask-driven
// gather from transposed weights. All variants accumulate in ascending k and
// differ only in exact +0.0 terms -> bitwise-identical results.
template <int LAYER, bool FORCE_DENSE>
__global__ void __launch_bounds__(256) step_kernel(
    const float* __restrict__ xext,
    const float* __restrict__ W,
    const float* __restrict__ bias,
    int t)
{
    // liveness: zero spikes in both layers at the previous boundary =>
    // all membranes <= THR and zero input forever => provably inert.
    if (LAYER == 1) {
        if (t > 0 && g_c1[t - 1] == 0 && g_c2[t - 1] == 0) return;
    } else {
        if (g_c1[t] == 0 && (t == 0 || g_c2[t - 1] == 0)) return;
    }

    constexpr int N  = (LAYER == 1) ? H1 : H2;
    constexpr int K  = (LAYER == 1) ? D1 : H1;
    constexpr int KW = K / 32;
    constexpr int MW = (LAYER == 1) ? MW1 : MW2;

    const float* A;
    int incnt;
    if (LAYER == 1) {
        if (t == 0) { A = xext; incnt = 0x40000000; }
        else        { A = g_s2; incnt = g_c2[t - 1]; }
    } else {
        A = g_s1; incnt = g_c1[t];
    }
    float* m    = (LAYER == 1) ? g_m1 : g_m2;
    float* sout = (LAYER == 1) ? g_s1 : g_s2;
    const unsigned* gmin = (LAYER == 1) ? g_mk2 : g_mk1;
    unsigned* gmout      = (LAYER == 1) ? g_mk1 : g_mk2;
    int* ocnt            = (LAYER == 1) ? &g_c1[t] : &g_c2[t];

    __shared__ __align__(16) unsigned char sraw[34 * 1024];
    float (*As)[128] = (float (*)[128])sraw;
    float (*Ws)[128] = (float (*)[128])(sraw + 8192);
    unsigned* smask  = (unsigned*)sraw;
    unsigned* stg    = (unsigned*)(sraw + 32768);
    __shared__ int wsum[8];
    __shared__ int nzk[2][16];

    const int tid = threadIdx.x;
    const int tx  = tid & 15;
    const int ty  = tid >> 4;
    const int bm  = blockIdx.y * 128;
    const int bn  = blockIdx.x * 128;

    float acc[8][8];
#pragma unroll
    for (int i = 0; i < 8; i++)
#pragma unroll
        for (int j = 0; j < 8; j++) acc[i][j] = 0.f;

    if (FORCE_DENSE) {
        // ---------- clean dense tiled GEMM ----------
        for (int k0 = 0; k0 < K; k0 += 16) {
#pragma unroll
            for (int l = 0; l < 2; l++) {
                int f   = tid + l * 256;
                int row = f >> 2;
                int kq  = (f & 3) * 4;
                float4 av = *(const float4*)&A[(bm + row) * K + k0 + kq];
                As[kq + 0][row] = av.x; As[kq + 1][row] = av.y;
                As[kq + 2][row] = av.z; As[kq + 3][row] = av.w;
                float4 wv = *(const float4*)&W[(bn + row) * K + k0 + kq];
                Ws[kq + 0][row] = wv.x; Ws[kq + 1][row] = wv.y;
                Ws[kq + 2][row] = wv.z; Ws[kq + 3][row] = wv.w;
            }
            __syncthreads();
#pragma unroll
            for (int kk = 0; kk < 16; kk++) {
                float4 a0 = *(const float4*)&As[kk][ty * 8];
                float4 a1 = *(const float4*)&As[kk][ty * 8 + 4];
                float4 b0 = *(const float4*)&Ws[kk][tx * 8];
                float4 b1 = *(const float4*)&Ws[kk][tx * 8 + 4];
                float a[8] = {a0.x, a0.y, a0.z, a0.w, a1.x, a1.y, a1.z, a1.w};
                float b[8] = {b0.x, b0.y, b0.z, b0.w, b1.x, b1.y, b1.z, b1.w};
#pragma unroll
                for (int i = 0; i < 8; i++)
#pragma unroll
                    for (int j = 0; j < 8; j++) acc[i][j] += a[i] * b[j];
            }
            __syncthreads();
        }
    } else if (incnt > SPARSE_THRESH) {
        // ---------- dense tiled GEMM with per-k-column zero skip ----------
        if (tid < 32) nzk[tid >> 4][tid & 15] = 0;
        __syncthreads();
        for (int k0 = 0; k0 < K; k0 += 16) {
            const int p = (k0 >> 4) & 1;
#pragma unroll
            for (int l = 0; l < 2; l++) {
                int f   = tid + l * 256;
                int row = f >> 2;
                int kq  = (f & 3) * 4;
                float4 av = *(const float4*)&A[(bm + row) * K + k0 + kq];
                As[kq + 0][row] = av.x; As[kq + 1][row] = av.y;
                As[kq + 2][row] = av.z; As[kq + 3][row] = av.w;
                if (av.x != 0.f) nzk[p][kq + 0] = 1;
                if (av.y != 0.f) nzk[p][kq + 1] = 1;
                if (av.z != 0.f) nzk[p][kq + 2] = 1;
                if (av.w != 0.f) nzk[p][kq + 3] = 1;
                float4 wv = *(const float4*)&W[(bn + row) * K + k0 + kq];
                Ws[kq + 0][row] = wv.x; Ws[kq + 1][row] = wv.y;
                Ws[kq + 2][row] = wv.z; Ws[kq + 3][row] = wv.w;
            }
            __syncthreads();
#pragma unroll
            for (int kk = 0; kk < 16; kk++) {
                if (nzk[p][kk]) {
                    float4 a0 = *(const float4*)&As[kk][ty * 8];
                    float4 a1 = *(const float4*)&As[kk][ty * 8 + 4];
                    float4 b0 = *(const float4*)&Ws[kk][tx * 8];
                    float4 b1 = *(const float4*)&Ws[kk][tx * 8 + 4];
                    float a[8] = {a0.x, a0.y, a0.z, a0.w, a1.x, a1.y, a1.z, a1.w};
                    float b[8] = {b0.x, b0.y, b0.z, b0.w, b1.x, b1.y, b1.z, b1.w};
#pragma unroll
                    for (int i = 0; i < 8; i++)
#pragma unroll
                        for (int j = 0; j < 8; j++) acc[i][j] += a[i] * b[j];
                }
            }
            if (tid < 16) nzk[p ^ 1][tid] = 0;
            __syncthreads();
        }
    } else if (incnt > 0) {
        // ---------- sparse gather from transposed weights (coalesced) ----------
        const float* WT = (LAYER == 1) ? g_W1T : g_W2T;   // [K][N]
        for (int idx = tid; idx < 128 * KW; idx += 256)
            smask[idx] = gmin[(bm + idx / KW) * KW + (idx % KW)];
        __syncthreads();
#pragma unroll
        for (int i = 0; i < 8; i++) {
            const unsigned* mrow = &smask[(ty * 8 + i) * KW];
            for (int w = 0; w < KW; w++) {
                unsigned word = mrow[w];
                while (word) {
                    int bit = __ffs(word) - 1;
                    word &= word - 1;
                    const float4* wp = (const float4*)&WT[(size_t)(w * 32 + bit) * N + bn + tx * 8];
                    float4 w0 = wp[0];
                    float4 w1 = wp[1];
                    acc[i][0] += w0.x; acc[i][1] += w0.y;
                    acc[i][2] += w0.z; acc[i][3] += w0.w;
                    acc[i][4] += w1.x; acc[i][5] += w1.y;
                    acc[i][6] += w1.z; acc[i][7] += w1.w;
                }
            }
        }
        __syncthreads();
    }
    // incnt == 0: acc stays 0 -> pure decay/reset epilogue

    // ---- epilogue: Leaky update + spike + mask staging ----
    if (tid < 256) { stg[tid] = 0u; stg[tid + 256] = 0u; }
    __syncthreads();

    int cnt = 0;
#pragma unroll
    for (int i = 0; i < 8; i++) {
        int row = bm + ty * 8 + i;
#pragma unroll
        for (int j = 0; j < 8; j++) {
            int col = bn + tx * 8 + j;
            int idx = row * N + col;
            float h  = acc[i][j] + bias[col];
            float mp = m[idx];
            float r  = (mp > THRV) ? 1.f : 0.f;
            float mn = BETAV * mp + h - r * THRV;
            float s  = (mn > THRV) ? 1.f : 0.f;
            m[idx]    = mn;
            sout[idx] = s;
            if (s != 0.f) {
                if (LAYER == 2) g_spk[idx] += 1.f;
                int cb = tx * 8 + j;
                atomicOr(&stg[(ty * 8 + i) * 4 + (cb >> 5)], 1u << (cb & 31));
                cnt++;
            }
        }
    }
    __syncthreads();

    for (int q = tid; q < 512; q += 256) {
        int r = q >> 2, w = q & 3;
        gmout[(bm + r) * MW + (bn >> 5) + w] = stg[q];
    }

#pragma unroll
    for (int o = 16; o > 0; o >>= 1) cnt += __shfl_down_sync(0xffffffff, cnt, o);
    if ((tid & 31) == 0) wsum[tid >> 5] = cnt;
    __syncthreads();
    if (tid == 0) {
        int tot = 0;
        for (int w = 0; w < 8; w++) tot += wsum[w];
        if (tot) atomicAdd(ocnt, tot);
    }
}

// out[B x 64] = (g_spk / NSTEPS) @ Wo^T + bo   (proven kernel)
__global__ void __launch_bounds__(256) final_kernel(
    const float* __restrict__ Wo, const float* __restrict__ bo,
    float* __restrict__ out)
{
    __shared__ float ssp[32][33];
    __shared__ float swo[64][33];
    const int tid  = threadIdx.x;
    const int row0 = blockIdx.x * 32;
    const int col  = tid & 63;
    const int rg   = tid >> 6;

    float acc[8];
#pragma unroll
    for (int r = 0; r < 8; r++) acc[r] = 0.f;

    for (int k0 = 0; k0 < H2; k0 += 32) {
        {
            int f = tid;
            int row = f >> 3;
            int kq  = (f & 7) * 4;
            float4 v = *(const float4*)&g_spk[(row0 + row) * H2 + k0 + kq];
            ssp[row][kq + 0] = v.x; ssp[row][kq + 1] = v.y;
            ssp[row][kq + 2] = v.z; ssp[row][kq + 3] = v.w;
        }
#pragma unroll
        for (int l = 0; l < 2; l++) {
            int f = tid + l * 256;
            int row = f >> 3;
            int kq  = (f & 7) * 4;
            float4 v = *(const float4*)&Wo[row * H2 + k0 + kq];
            swo[row][kq + 0] = v.x; swo[row][kq + 1] = v.y;
            swo[row][kq + 2] = v.z; swo[row][kq + 3] = v.w;
        }
        __syncthreads();
#pragma unroll 8
        for (int kk = 0; kk < 32; kk++) {
            float w = swo[col][kk];
#pragma unroll
            for (int r = 0; r < 8; r++) acc[r] += ssp[rg + r * 4][kk] * w;
        }
        __syncthreads();
    }
#pragma unroll
    for (int r = 0; r < 8; r++)
        out[(row0 + rg + r * 4) * 64 + col] = acc[r] * (1.0f / NSTEPS) + bo[col];
}

extern "C" void kernel_launch(void* const* d_in, const int* in_sizes, int n_in,
                              void* d_out, int out_size)
{
    const float* x  = (const float*)d_in[0];
    const float* W1 = (const float*)d_in[1];
    const float* b1 = (const float*)d_in[2];
    const float* W2 = (const float*)d_in[3];
    const float* b2 = (const float*)d_in[4];
    const float* Wo = (const float*)d_in[5];
    const float* bo = (const float*)d_in[6];
    float* out = (float*)d_out;

    init_kernel<<<2048, 256>>>(W1, W2);
    // t = 0: dense (x is dense; s1 at ~6% density never skips anyway)
    step_kernel<1, true><<<dim3(H1 / 128, Bsz / 128), 256>>>(x, W1, b1, 0);
    step_kernel<2, true><<<dim3(H2 / 128, Bsz / 128), 256>>>(x, W2, b2, 0);
    for (int t = 1; t < NSTEPS; t++) {
        step_kernel<1, false><<<dim3(H1 / 128, Bsz / 128), 256>>>(x, W1, b1, t);
        step_kernel<2, false><<<dim3(H2 / 128, Bsz / 128), 256>>>(x, W2, b2, t);
    }
    final_kernel<<<Bsz / 32, 256>>>(Wo, bo, out);
}

// round 9
// speedup vs baseline: 1.6620x; 1.0002x over previous
#include <cuda_runtime.h>

#define Bsz 4096
#define D1  1024   // layer-1 K
#define H1  2048
#define H2  1024
#define NSTEPS 20
#define THRV 1.0f
#define BETAV 0.9f
#define SPARSE_THRESH 8192

#define MW1 (H1/32)   // 64 mask words per s1 row
#define MW2 (H2/32)   // 32 mask words per s2 row

// ---- persistent scratch (no allocs allowed) ----
__device__ float g_m1[Bsz * H1];
__device__ float g_m2[Bsz * H2];
__device__ float g_spk[Bsz * H2];
__device__ float g_s1[Bsz * H1];
__device__ float g_s2[Bsz * H2];
__device__ float g_W1T[D1 * H1];        // W1T[c*H1+n] = W1[n*D1+c]
__device__ float g_W2T[H1 * H2];        // W2T[c*H2+n] = W2[n*H1+c]
__device__ unsigned g_mk1[Bsz * MW1];   // s1 spike bitmasks (rewritten each step)
__device__ unsigned g_mk2[Bsz * MW2];   // s2 spike bitmasks
__device__ int   g_c1[NSTEPS];
__device__ int   g_c2[NSTEPS];

__global__ void init_kernel(const float* __restrict__ W1,
                            const float* __restrict__ W2) {
    int idx = blockIdx.x * blockDim.x + threadIdx.x;
    int stride = gridDim.x * blockDim.x;
    for (int i = idx; i < Bsz * H1; i += stride) g_m1[i] = 0.f;
    for (int i = idx; i < Bsz * H2; i += stride) { g_m2[i] = 0.f; g_spk[i] = 0.f; }
    // transposes: write-coalesced (n fastest), reads strided (one-time cost)
    for (int i = idx; i < D1 * H1; i += stride) {
        int c = i / H1, n = i % H1;
        g_W1T[i] = W1[n * D1 + c];
    }
    for (int i = idx; i < H1 * H2; i += stride) {
        int c = i / H2, n = i % H2;
        g_W2T[i] = W2[n * H1 + c];
    }
    if (idx < NSTEPS) { g_c1[idx] = 0; g_c2[idx] = 0; }
}

// Fused linear (h = A @ W^T + bias) + Leaky update + spike/mask write + count.
// FORCE_DENSE (t==0): clean dense tiled GEMM (no nzk overhead).
// Otherwise: dense-with-nzk fallback (incnt large) or coalesced mask-driven
// gather from transposed weights. All variants accumulate in ascending k and
// differ only in exact +0.0 terms -> bitwise-identical results.
template <int LAYER, bool FORCE_DENSE>
__global__ void __launch_bounds__(256) step_kernel(
    const float* __restrict__ xext,
    const float* __restrict__ W,
    const float* __restrict__ bias,
    int t)
{
    // liveness: zero spikes in both layers at the previous boundary =>
    // all membranes <= THR and zero input forever => provably inert.
    if (LAYER == 1) {
        if (t > 0 && g_c1[t - 1] == 0 && g_c2[t - 1] == 0) return;
    } else {
        if (g_c1[t] == 0 && (t == 0 || g_c2[t - 1] == 0)) return;
    }

    constexpr int N  = (LAYER == 1) ? H1 : H2;
    constexpr int K  = (LAYER == 1) ? D1 : H1;
    constexpr int KW = K / 32;
    constexpr int MW = (LAYER == 1) ? MW1 : MW2;

    const float* A;
    int incnt;
    if (LAYER == 1) {
        if (t == 0) { A = xext; incnt = 0x40000000; }
        else        { A = g_s2; incnt = g_c2[t - 1]; }
    } else {
        A = g_s1; incnt = g_c1[t];
    }
    float* m    = (LAYER == 1) ? g_m1 : g_m2;
    float* sout = (LAYER == 1) ? g_s1 : g_s2;
    const unsigned* gmin = (LAYER == 1) ? g_mk2 : g_mk1;
    unsigned* gmout      = (LAYER == 1) ? g_mk1 : g_mk2;
    int* ocnt            = (LAYER == 1) ? &g_c1[t] : &g_c2[t];

    __shared__ __align__(16) unsigned char sraw[34 * 1024];
    float (*As)[128] = (float (*)[128])sraw;
    float (*Ws)[128] = (float (*)[128])(sraw + 8192);
    unsigned* smask  = (unsigned*)sraw;
    unsigned* stg    = (unsigned*)(sraw + 32768);
    __shared__ int wsum[8];
    __shared__ int nzk[2][16];

    const int tid = threadIdx.x;
    const int tx  = tid & 15;
    const int ty  = tid >> 4;
    const int bm  = blockIdx.y * 128;
    const int bn  = blockIdx.x * 128;

    float acc[8][8];
#pragma unroll
    for (int i = 0; i < 8; i++)
#pragma unroll
        for (int j = 0; j < 8; j++) acc[i][j] = 0.f;

    if (FORCE_DENSE) {
        // ---------- clean dense tiled GEMM ----------
        for (int k0 = 0; k0 < K; k0 += 16) {
#pragma unroll
            for (int l = 0; l < 2; l++) {
                int f   = tid + l * 256;
                int row = f >> 2;
                int kq  = (f & 3) * 4;
                float4 av = *(const float4*)&A[(bm + row) * K + k0 + kq];
                As[kq + 0][row] = av.x; As[kq + 1][row] = av.y;
                As[kq + 2][row] = av.z; As[kq + 3][row] = av.w;
                float4 wv = *(const float4*)&W[(bn + row) * K + k0 + kq];
                Ws[kq + 0][row] = wv.x; Ws[kq + 1][row] = wv.y;
                Ws[kq + 2][row] = wv.z; Ws[kq + 3][row] = wv.w;
            }
            __syncthreads();
#pragma unroll
            for (int kk = 0; kk < 16; kk++) {
                float4 a0 = *(const float4*)&As[kk][ty * 8];
                float4 a1 = *(const float4*)&As[kk][ty * 8 + 4];
                float4 b0 = *(const float4*)&Ws[kk][tx * 8];
                float4 b1 = *(const float4*)&Ws[kk][tx * 8 + 4];
                float a[8] = {a0.x, a0.y, a0.z, a0.w, a1.x, a1.y, a1.z, a1.w};
                float b[8] = {b0.x, b0.y, b0.z, b0.w, b1.x, b1.y, b1.z, b1.w};
#pragma unroll
                for (int i = 0; i < 8; i++)
#pragma unroll
                    for (int j = 0; j < 8; j++) acc[i][j] += a[i] * b[j];
            }
            __syncthreads();
        }
    } else if (incnt > SPARSE_THRESH) {
        // ---------- dense tiled GEMM with per-k-column zero skip ----------
        if (tid < 32) nzk[tid >> 4][tid & 15] = 0;
        __syncthreads();
        for (int k0 = 0; k0 < K; k0 += 16) {
            const int p = (k0 >> 4) & 1;
#pragma unroll
            for (int l = 0; l < 2; l++) {
                int f   = tid + l * 256;
                int row = f >> 2;
                int kq  = (f & 3) * 4;
                float4 av = *(const float4*)&A[(bm + row) * K + k0 + kq];
                As[kq + 0][row] = av.x; As[kq + 1][row] = av.y;
                As[kq + 2][row] = av.z; As[kq + 3][row] = av.w;
                if (av.x != 0.f) nzk[p][kq + 0] = 1;
                if (av.y != 0.f) nzk[p][kq + 1] = 1;
                if (av.z != 0.f) nzk[p][kq + 2] = 1;
                if (av.w != 0.f) nzk[p][kq + 3] = 1;
                float4 wv = *(const float4*)&W[(bn + row) * K + k0 + kq];
                Ws[kq + 0][row] = wv.x; Ws[kq + 1][row] = wv.y;
                Ws[kq + 2][row] = wv.z; Ws[kq + 3][row] = wv.w;
            }
            __syncthreads();
#pragma unroll
            for (int kk = 0; kk < 16; kk++) {
                if (nzk[p][kk]) {
                    float4 a0 = *(const float4*)&As[kk][ty * 8];
                    float4 a1 = *(const float4*)&As[kk][ty * 8 + 4];
                    float4 b0 = *(const float4*)&Ws[kk][tx * 8];
                    float4 b1 = *(const float4*)&Ws[kk][tx * 8 + 4];
                    float a[8] = {a0.x, a0.y, a0.z, a0.w, a1.x, a1.y, a1.z, a1.w};
                    float b[8] = {b0.x, b0.y, b0.z, b0.w, b1.x, b1.y, b1.z, b1.w};
#pragma unroll
                    for (int i = 0; i < 8; i++)
#pragma unroll
                        for (int j = 0; j < 8; j++) acc[i][j] += a[i] * b[j];
                }
            }
            if (tid < 16) nzk[p ^ 1][tid] = 0;
            __syncthreads();
        }
    } else if (incnt > 0) {
        // ---------- sparse gather from transposed weights (coalesced) ----------
        const float* WT = (LAYER == 1) ? g_W1T : g_W2T;   // [K][N]
        for (int idx = tid; idx < 128 * KW; idx += 256)
            smask[idx] = gmin[(bm + idx / KW) * KW + (idx % KW)];
        __syncthreads();
#pragma unroll
        for (int i = 0; i < 8; i++) {
            const unsigned* mrow = &smask[(ty * 8 + i) * KW];
            for (int w = 0; w < KW; w++) {
                unsigned word = mrow[w];
                while (word) {
                    int bit = __ffs(word) - 1;
                    word &= word - 1;
                    const float4* wp = (const float4*)&WT[(size_t)(w * 32 + bit) * N + bn + tx * 8];
                    float4 w0 = wp[0];
                    float4 w1 = wp[1];
                    acc[i][0] += w0.x; acc[i][1] += w0.y;
                    acc[i][2] += w0.z; acc[i][3] += w0.w;
                    acc[i][4] += w1.x; acc[i][5] += w1.y;
                    acc[i][6] += w1.z; acc[i][7] += w1.w;
                }
            }
        }
        __syncthreads();
    }
    // incnt == 0: acc stays 0 -> pure decay/reset epilogue

    // ---- epilogue: Leaky update + spike + mask staging ----
    if (tid < 256) { stg[tid] = 0u; stg[tid + 256] = 0u; }
    __syncthreads();

    int cnt = 0;
#pragma unroll
    for (int i = 0; i < 8; i++) {
        int row = bm + ty * 8 + i;
#pragma unroll
        for (int j = 0; j < 8; j++) {
            int col = bn + tx * 8 + j;
            int idx = row * N + col;
            float h  = acc[i][j] + bias[col];
            float mp = m[idx];
            float r  = (mp > THRV) ? 1.f : 0.f;
            float mn = BETAV * mp + h - r * THRV;
            float s  = (mn > THRV) ? 1.f : 0.f;
            m[idx]    = mn;
            sout[idx] = s;
            if (s != 0.f) {
                if (LAYER == 2) g_spk[idx] += 1.f;
                int cb = tx * 8 + j;
                atomicOr(&stg[(ty * 8 + i) * 4 + (cb >> 5)], 1u << (cb & 31));
                cnt++;
            }
        }
    }
    __syncthreads();

    for (int q = tid; q < 512; q += 256) {
        int r = q >> 2, w = q & 3;
        gmout[(bm + r) * MW + (bn >> 5) + w] = stg[q];
    }

#pragma unroll
    for (int o = 16; o > 0; o >>= 1) cnt += __shfl_down_sync(0xffffffff, cnt, o);
    if ((tid & 31) == 0) wsum[tid >> 5] = cnt;
    __syncthreads();
    if (tid == 0) {
        int tot = 0;
        for (int w = 0; w < 8; w++) tot += wsum[w];
        if (tot) atomicAdd(ocnt, tot);
    }
}

// out[B x 64] = (g_spk / NSTEPS) @ Wo^T + bo   (proven kernel)
__global__ void __launch_bounds__(256) final_kernel(
    const float* __restrict__ Wo, const float* __restrict__ bo,
    float* __restrict__ out)
{
    __shared__ float ssp[32][33];
    __shared__ float swo[64][33];
    const int tid  = threadIdx.x;
    const int row0 = blockIdx.x * 32;
    const int col  = tid & 63;
    const int rg   = tid >> 6;

    float acc[8];
#pragma unroll
    for (int r = 0; r < 8; r++) acc[r] = 0.f;

    for (int k0 = 0; k0 < H2; k0 += 32) {
        {
            int f = tid;
            int row = f >> 3;
            int kq  = (f & 7) * 4;
            float4 v = *(const float4*)&g_spk[(row0 + row) * H2 + k0 + kq];
            ssp[row][kq + 0] = v.x; ssp[row][kq + 1] = v.y;
            ssp[row][kq + 2] = v.z; ssp[row][kq + 3] = v.w;
        }
#pragma unroll
        for (int l = 0; l < 2; l++) {
            int f = tid + l * 256;
            int row = f >> 3;
            int kq  = (f & 7) * 4;
            float4 v = *(const float4*)&Wo[row * H2 + k0 + kq];
            swo[row][kq + 0] = v.x; swo[row][kq + 1] = v.y;
            swo[row][kq + 2] = v.z; swo[row][kq + 3] = v.w;
        }
        __syncthreads();
#pragma unroll 8
        for (int kk = 0; kk < 32; kk++) {
            float w = swo[col][kk];
#pragma unroll
            for (int r = 0; r < 8; r++) acc[r] += ssp[rg + r * 4][kk] * w;
        }
        __syncthreads();
    }
#pragma unroll
    for (int r = 0; r < 8; r++)
        out[(row0 + rg + r * 4) * 64 + col] = acc[r] * (1.0f / NSTEPS) + bo[col];
}

extern "C" void kernel_launch(void* const* d_in, const int* in_sizes, int n_in,
                              void* d_out, int out_size)
{
    const float* x  = (const float*)d_in[0];
    const float* W1 = (const float*)d_in[1];
    const float* b1 = (const float*)d_in[2];
    const float* W2 = (const float*)d_in[3];
    const float* b2 = (const float*)d_in[4];
    const float* Wo = (const float*)d_in[5];
    const float* bo = (const float*)d_in[6];
    float* out = (float*)d_out;

    init_kernel<<<2048, 256>>>(W1, W2);
    // t = 0: dense (x is dense; s1 at ~6% density never skips anyway)
    step_kernel<1, true><<<dim3(H1 / 128, Bsz / 128), 256>>>(x, W1, b1, 0);
    step_kernel<2, true><<<dim3(H2 / 128, Bsz / 128), 256>>>(x, W2, b2, 0);
    for (int t = 1; t < NSTEPS; t++) {
        step_kernel<1, false><<<dim3(H1 / 128, Bsz / 128), 256>>>(x, W1, b1, t);
        step_kernel<2, false><<<dim3(H2 / 128, Bsz / 128), 256>>>(x, W2, b2, t);
    }
    final_kernel<<<Bsz / 32, 256>>>(Wo, bo, out);
}